// round 1
// baseline (speedup 1.0000x reference)
#include <cuda_runtime.h>
#include <cstdint>

#define BB 4
#define QQ 1024
#define KKEYS 2048
#define NB 16
#define VD 512

// Per-row max of prod (scratch; written by prod_kernel, read by norm_kernel).
__device__ float g_rowmax[BB * QQ];

// ---------------------------------------------------------------------------
// Kernel 1: compute prod_k = PROD_n ((1 - |q_n - k_n|) + 1e-8) for a tile of
// 16 q-rows x all 2048 keys. Writes raw prods into the weights region and the
// per-row max into g_rowmax.  Thread map: qy = tid/16 (q row), kx = tid%16
// (key lane). Each q row is fully owned by 16 lanes of one warp-half -> the
// row max is computed with shfl, no atomics needed.
// ---------------------------------------------------------------------------
__global__ void __launch_bounds__(256) prod_kernel(
    const float* __restrict__ qbits,
    const float* __restrict__ kbits,
    const int*   __restrict__ mask,
    float*       __restrict__ W)
{
    __shared__ float skey[512 * 17];   // pad 17 -> conflict-free column reads
    __shared__ int   smask[512];

    const int tid = threadIdx.x;
    const int b   = blockIdx.x >> 6;        // 64 q-tiles per batch
    const int qt  = blockIdx.x & 63;
    const int qy  = tid >> 4;
    const int kx  = tid & 15;
    const int q   = qt * 16 + qy;

    float qreg[NB];
#pragma unroll
    for (int i = 0; i < NB; i++)
        qreg[i] = qbits[(b * QQ + q) * NB + i];

    const float* kbase = kbits + (size_t)b * KKEYS * NB;
    float* wrow = W + (size_t)(b * QQ + q) * KKEYS;

    float maxp = 0.0f;

    for (int c = 0; c < KKEYS / 512; c++) {
        // stage 512 keys x 16 bits, coalesced global reads
        for (int i = tid; i < 512 * 16; i += 256) {
            int k = i >> 4, bit = i & 15;
            skey[k * 17 + bit] = kbase[(c * 512 + k) * 16 + bit];
        }
        for (int i = tid; i < 512; i += 256)
            smask[i] = mask[b * KKEYS + c * 512 + i];
        __syncthreads();

#pragma unroll 4
        for (int kk = 0; kk < 32; kk++) {
            const int kl = kk * 16 + kx;
            const float* kr = &skey[kl * 17];
            float p = 1.0f;
#pragma unroll
            for (int bit = 0; bit < NB; bit++) {
                float d = qreg[bit] - kr[bit];
                // match reference rounding: (1 - |d|) first, THEN + eps
                float t = (1.0f - fabsf(d)) + 1e-8f;
                p *= t;
            }
            if (smask[kl] == 0) p = 0.0f;
            wrow[c * 512 + kl] = p;
            maxp = fmaxf(maxp, p);
        }
        __syncthreads();
    }

    // reduce max across the 16 kx lanes (same half-warp)
#pragma unroll
    for (int off = 1; off < 16; off <<= 1)
        maxp = fmaxf(maxp, __shfl_xor_sync(0xffffffffu, maxp, off));
    if (kx == 0)
        g_rowmax[b * QQ + q] = maxp;
}

// ---------------------------------------------------------------------------
// Kernel 2: softmax without exp/log.
//   weight_k = (prod_k / max)^10 / sum_k (prod_k / max)^10
// (score = log(prod)/0.1 => exp(score - max_score) = (prod/maxprod)^10).
// One block per (b,q) row, 8 keys/thread held in registers.
// ---------------------------------------------------------------------------
__global__ void __launch_bounds__(256) norm_kernel(float* __restrict__ W)
{
    const int row = blockIdx.x;
    const int tid = threadIdx.x;
    float* wr = W + (size_t)row * KKEYS;

    const float m    = g_rowmax[row];
    const float invm = 1.0f / m;

    float r10v[8];
    float lsum = 0.0f;
#pragma unroll
    for (int i = 0; i < 8; i++) {
        float p  = wr[tid + i * 256];
        float r  = p * invm;
        float r2 = r * r, r4 = r2 * r2, r8 = r4 * r4;
        float r10 = r8 * r2;      // r^10
        r10v[i] = r10;
        lsum += r10;
    }

    __shared__ float red[8];
    __shared__ float s_inv;
#pragma unroll
    for (int off = 16; off; off >>= 1)
        lsum += __shfl_xor_sync(0xffffffffu, lsum, off);
    if ((tid & 31) == 0) red[tid >> 5] = lsum;
    __syncthreads();
    if (tid < 32) {
        float v = (tid < 8) ? red[tid] : 0.0f;
#pragma unroll
        for (int off = 4; off; off >>= 1)
            v += __shfl_xor_sync(0xffffffffu, v, off);
        if (tid == 0) s_inv = 1.0f / v;
    }
    __syncthreads();
    const float invs = s_inv;

#pragma unroll
    for (int i = 0; i < 8; i++)
        wr[tid + i * 256] = r10v[i] * invs;
}

// ---------------------------------------------------------------------------
// Kernel 3: batched fp32 GEMM  out[b] = W[b] (1024x2048) * V[b] (2048x512).
// 128x128 tile, BK=16, 8x8 per thread, 256 threads, smem padded to 132.
// ---------------------------------------------------------------------------
__global__ void __launch_bounds__(256) gemm_kernel(
    const float* __restrict__ Wf,
    const float* __restrict__ Vf,
    float*       __restrict__ Out)
{
    __shared__ float As[16][132];   // [k][m], padded
    __shared__ float Bs[16][132];   // [k][n], padded

    const int b  = blockIdx.z;
    const int bm = blockIdx.y * 128;
    const int bn = blockIdx.x * 128;
    const int tid = threadIdx.x;
    const int tx = tid & 15, ty = tid >> 4;

    const float* A  = Wf + (size_t)b * QQ * KKEYS;
    const float* Bv = Vf + (size_t)b * KKEYS * VD;
    float*       C  = Out + (size_t)b * QQ * VD;

    float acc[8][8];
#pragma unroll
    for (int i = 0; i < 8; i++)
#pragma unroll
        for (int j = 0; j < 8; j++) acc[i][j] = 0.0f;

    for (int ko = 0; ko < KKEYS; ko += 16) {
        // A tile: 128 rows x 16 k, as float4, stored transposed into As[k][m]
#pragma unroll
        for (int i = 0; i < 2; i++) {
            int f = tid + i * 256;            // 0..511 float4 slots
            int row = f >> 2, c4 = f & 3;
            float4 v = *(const float4*)&A[(size_t)(bm + row) * KKEYS + ko + c4 * 4];
            As[c4 * 4 + 0][row] = v.x;
            As[c4 * 4 + 1][row] = v.y;
            As[c4 * 4 + 2][row] = v.z;
            As[c4 * 4 + 3][row] = v.w;
        }
        // B tile: 16 k-rows x 128 cols, direct float4 stores
#pragma unroll
        for (int i = 0; i < 2; i++) {
            int f = tid + i * 256;
            int row = f >> 5, c4 = f & 31;
            float4 v = *(const float4*)&Bv[(size_t)(ko + row) * VD + bn + c4 * 4];
            *(float4*)&Bs[row][c4 * 4] = v;
        }
        __syncthreads();

#pragma unroll
        for (int k = 0; k < 16; k++) {
            float4 a0 = *(const float4*)&As[k][ty * 8];
            float4 a1 = *(const float4*)&As[k][ty * 8 + 4];
            float4 b0 = *(const float4*)&Bs[k][tx * 8];
            float4 b1 = *(const float4*)&Bs[k][tx * 8 + 4];
            float a[8] = {a0.x, a0.y, a0.z, a0.w, a1.x, a1.y, a1.z, a1.w};
            float bb[8] = {b0.x, b0.y, b0.z, b0.w, b1.x, b1.y, b1.z, b1.w};
#pragma unroll
            for (int i = 0; i < 8; i++)
#pragma unroll
                for (int j = 0; j < 8; j++)
                    acc[i][j] += a[i] * bb[j];
        }
        __syncthreads();
    }

#pragma unroll
    for (int i = 0; i < 8; i++) {
        int row = bm + ty * 8 + i;
        float* cp = &C[(size_t)row * VD + bn + tx * 8];
        float4 v0 = make_float4(acc[i][0], acc[i][1], acc[i][2], acc[i][3]);
        float4 v1 = make_float4(acc[i][4], acc[i][5], acc[i][6], acc[i][7]);
        *(float4*)cp       = v0;
        *(float4*)(cp + 4) = v1;
    }
}

// ---------------------------------------------------------------------------
// Launch: out layout = [output (B,Q,V) | weights (B,Q,K)] per reference tuple.
// ---------------------------------------------------------------------------
extern "C" void kernel_launch(void* const* d_in, const int* in_sizes, int n_in,
                              void* d_out, int out_size)
{
    (void)in_sizes; (void)n_in; (void)out_size;
    const float* qb   = (const float*)d_in[0];
    const float* kb   = (const float*)d_in[1];
    const float* vals = (const float*)d_in[2];
    const int*   mask = (const int*)d_in[3];

    float* out = (float*)d_out;
    float* W   = out + (size_t)BB * QQ * VD;   // weights region

    prod_kernel<<<BB * (QQ / 16), 256>>>(qb, kb, mask, W);
    norm_kernel<<<BB * QQ, 256>>>(W);
    dim3 g(VD / 128, QQ / 128, BB);
    gemm_kernel<<<g, 256>>>(W, vals, out);
}

// round 2
// speedup vs baseline: 4.7556x; 4.7556x over previous
#include <cuda_runtime.h>
#include <cstdint>

#define BB 4
#define QQ 1024
#define KKEYS 2048
#define NB 16
#define VD 512

// Per-row max of prod (scratch; written by prod_kernel, read by norm_gemv).
__device__ float g_rowmax[BB * QQ];

// ---------------------------------------------------------------------------
// Kernel 1: prod_k = PROD_n ((1 - |q_n - k_n|) + 1e-8) for 8 q-rows x 2048
// keys per block (grid = 512 for occupancy). Thread map: qy = tid>>5 (q row),
// kx = tid&31 (key lane) -> each q row owned by one full warp, row-max via
// shfl. Pairwise-tree product (depth 4) for ILP. Keys staged in smem padded
// to 20 floats/key: conflict-free LDS.128.
// ---------------------------------------------------------------------------
__global__ void __launch_bounds__(256) prod_kernel(
    const float* __restrict__ qbits,
    const float* __restrict__ kbits,
    const int*   __restrict__ mask,
    float*       __restrict__ W)
{
    __shared__ float skey[512 * 20];   // pad 20: float4-aligned, conflict-free
    __shared__ int   smask[512];

    const int tid = threadIdx.x;
    const int b   = blockIdx.x >> 7;        // 128 q-tiles of 8 per batch
    const int qt  = blockIdx.x & 127;
    const int qy  = tid >> 5;
    const int kx  = tid & 31;
    const int q   = qt * 8 + qy;

    // query bits (broadcast within warp -> L1 served)
    float qreg[NB];
    {
        const float4* q4 = (const float4*)(qbits + (size_t)(b * QQ + q) * NB);
#pragma unroll
        for (int j = 0; j < 4; j++) {
            float4 v = q4[j];
            qreg[j * 4 + 0] = v.x; qreg[j * 4 + 1] = v.y;
            qreg[j * 4 + 2] = v.z; qreg[j * 4 + 3] = v.w;
        }
    }

    const float4* kbase4 = (const float4*)(kbits + (size_t)b * KKEYS * NB);
    float* wrow = W + (size_t)(b * QQ + q) * KKEYS;

    float maxp = 0.0f;

    for (int c = 0; c < KKEYS / 512; c++) {
        // stage 512 keys x 16 bits as float4 (coalesced)
#pragma unroll
        for (int it = 0; it < 8; it++) {
            int i = tid + it * 256;           // 0..2047 float4 slots
            int k = i >> 2, j = i & 3;
            float4 v = kbase4[(size_t)(c * 512 + k) * 4 + j];
            *(float4*)&skey[k * 20 + j * 4] = v;
        }
        for (int i = tid; i < 512; i += 256)
            smask[i] = mask[b * KKEYS + c * 512 + i];
        __syncthreads();

#pragma unroll 4
        for (int kk = 0; kk < 16; kk++) {
            const int kl = kk * 32 + kx;
            const float* kr = &skey[kl * 20];
            float4 k0 = *(const float4*)&kr[0];
            float4 k1 = *(const float4*)&kr[4];
            float4 k2 = *(const float4*)&kr[8];
            float4 k3 = *(const float4*)&kr[12];
            float kv[NB] = {k0.x,k0.y,k0.z,k0.w, k1.x,k1.y,k1.z,k1.w,
                            k2.x,k2.y,k2.z,k2.w, k3.x,k3.y,k3.z,k3.w};
            float t[NB];
#pragma unroll
            for (int bit = 0; bit < NB; bit++) {
                float d = qreg[bit] - kv[bit];
                t[bit] = (1.0f - fabsf(d)) + 1e-8f;   // match ref rounding
            }
            // pairwise tree product, depth 4
            float m0 = (t[0]*t[1]) * (t[2]*t[3]);
            float m1 = (t[4]*t[5]) * (t[6]*t[7]);
            float m2 = (t[8]*t[9]) * (t[10]*t[11]);
            float m3 = (t[12]*t[13]) * (t[14]*t[15]);
            float p  = (m0 * m1) * (m2 * m3);
            if (smask[kl] == 0) p = 0.0f;
            wrow[c * 512 + kl] = p;
            maxp = fmaxf(maxp, p);
        }
        __syncthreads();
    }

    // reduce max across the 32 lanes of this row's warp
#pragma unroll
    for (int off = 16; off; off >>= 1)
        maxp = fmaxf(maxp, __shfl_xor_sync(0xffffffffu, maxp, off));
    if (kx == 0)
        g_rowmax[b * QQ + q] = maxp;
}

// ---------------------------------------------------------------------------
// Kernel 2: fused softmax-normalize + sparse GEMV.
//   weight_k = (p_k / max)^10 / sum
// Writes all 2048 normalized weights (exact), then compacts keys with
// weight > TAU into smem and computes out[row,:] = sum w_k * V[k,:] over the
// selected set only. Tail mass below TAU is ~1e-5 -> far under 1e-3 rel_err.
// One block per (b,q) row.
// ---------------------------------------------------------------------------
#define TAU 2e-7f

__global__ void __launch_bounds__(256) norm_gemv_kernel(
    float*       __restrict__ W,
    const float* __restrict__ Vf,
    float*       __restrict__ Out)
{
    __shared__ float sw[KKEYS];
    __shared__ int   sidx[KKEYS];
    __shared__ int   scnt;
    __shared__ float red[8];
    __shared__ float s_inv;

    const int row = blockIdx.x;
    const int b   = row >> 10;
    const int tid = threadIdx.x;
    float* wr = W + (size_t)row * KKEYS;

    if (tid == 0) scnt = 0;

    const float m    = g_rowmax[row];
    const float invm = 1.0f / m;

    float r10v[8];
    float lsum = 0.0f;
#pragma unroll
    for (int i = 0; i < 8; i++) {
        float p  = wr[tid + i * 256];
        float r  = p * invm;
        float r2 = r * r, r4 = r2 * r2, r8 = r4 * r4;
        float r10 = r8 * r2;      // r^10
        r10v[i] = r10;
        lsum += r10;
    }

#pragma unroll
    for (int off = 16; off; off >>= 1)
        lsum += __shfl_xor_sync(0xffffffffu, lsum, off);
    if ((tid & 31) == 0) red[tid >> 5] = lsum;
    __syncthreads();
    if (tid < 32) {
        float v = (tid < 8) ? red[tid] : 0.0f;
#pragma unroll
        for (int off = 4; off; off >>= 1)
            v += __shfl_xor_sync(0xffffffffu, v, off);
        if (tid == 0) s_inv = 1.0f / v;
    }
    __syncthreads();
    const float invs = s_inv;

    // write normalized weights + compact significant keys
#pragma unroll
    for (int i = 0; i < 8; i++) {
        float w = r10v[i] * invs;
        wr[tid + i * 256] = w;
        if (w > TAU) {
            int p = atomicAdd(&scnt, 1);
            sw[p]   = w;
            sidx[p] = tid + i * 256;
        }
    }
    __syncthreads();

    // sparse GEMV: out[row, :] = sum_s w_s * V[k_s, :]
    const int S = scnt;
    const float* V = Vf + (size_t)b * KKEYS * VD;
    float acc0 = 0.0f, acc1 = 0.0f;
#pragma unroll 4
    for (int s = 0; s < S; s++) {
        float w = sw[s];
        const float* vrow = V + (size_t)sidx[s] * VD;
        acc0 += w * vrow[tid];
        acc1 += w * vrow[tid + 256];
    }
    Out[(size_t)row * VD + tid]       = acc0;
    Out[(size_t)row * VD + 256 + tid] = acc1;
}

// ---------------------------------------------------------------------------
// Launch: out layout = [output (B,Q,V) | weights (B,Q,K)] per reference tuple.
// ---------------------------------------------------------------------------
extern "C" void kernel_launch(void* const* d_in, const int* in_sizes, int n_in,
                              void* d_out, int out_size)
{
    (void)in_sizes; (void)n_in; (void)out_size;
    const float* qb   = (const float*)d_in[0];
    const float* kb   = (const float*)d_in[1];
    const float* vals = (const float*)d_in[2];
    const int*   mask = (const int*)d_in[3];

    float* out = (float*)d_out;
    float* W   = out + (size_t)BB * QQ * VD;   // weights region

    prod_kernel<<<BB * (QQ / 8), 256>>>(qb, kb, mask, W);
    norm_gemv_kernel<<<BB * QQ, 256>>>(W, vals, out);
}